// round 1
// baseline (speedup 1.0000x reference)
#include <cuda_runtime.h>
#include <cuda_bf16.h>
#include <math.h>

// Problem constants (fixed by the reference)
#define N_USERS 100000
#define N_ITEMS 50000
#define BATCH   64
#define ORDER   8

// Scratch: device globals (no allocation allowed).
// Layout: item-major [N][64] for dense states so each edge touches 256
// contiguous bytes.
__device__ __align__(16) float g_b0[N_ITEMS * BATCH];
__device__ __align__(16) float g_b1[N_ITEMS * BATCH];
__device__ __align__(16) float g_b2[N_ITEMS * BATCH];
__device__ __align__(16) float g_acc[N_ITEMS * BATCH];
__device__ __align__(16) float g_y[N_USERS * BATCH];
__device__ __align__(16) float g_z[N_ITEMS * BATCH];

// ---------------------------------------------------------------------------
// Zero a buffer (float4-vectorized)
__global__ void zero_k(float4* __restrict__ p, int n4) {
    int i = blockIdx.x * blockDim.x + threadIdx.x;
    if (i < n4) p[i] = make_float4(0.f, 0.f, 0.f, 0.f);
}

// ---------------------------------------------------------------------------
// Scatter SpMM: for each edge e: y[dst[e]][:] += vals[e] * x[src[e]][:]
// 16 threads per edge, each owns one float4 (4 of the 64 batch lanes).
// Gather is coalesced (16 lanes x 16B = 256B contiguous); scatter uses
// red.global.add.v4.f32 (sm_90+), one 16B reduction per thread.
__global__ void spmm_scatter(const float* __restrict__ x,
                             float* __restrict__ y,
                             const float* __restrict__ vals,
                             const int* __restrict__ src,
                             const int* __restrict__ dst,
                             int nnz) {
    int tid = blockIdx.x * blockDim.x + threadIdx.x;
    int e = tid >> 4;
    if (e >= nnz) return;
    int t = tid & 15;

    float v = __ldg(vals + e);
    int s = __ldg(src + e);
    int d = __ldg(dst + e);

    const float4* xp = reinterpret_cast<const float4*>(x + (size_t)s * BATCH);
    float4 xv = __ldg(xp + t);

    float4 r;
    r.x = v * xv.x; r.y = v * xv.y; r.z = v * xv.z; r.w = v * xv.w;

    float* addr = y + (size_t)d * BATCH + t * 4;
    asm volatile("red.global.add.v4.f32 [%0], {%1, %2, %3, %4};"
                 :: "l"(addr), "f"(r.x), "f"(r.y), "f"(r.z), "f"(r.w)
                 : "memory");
}

// ---------------------------------------------------------------------------
// First Chebyshev step:  t1 = s - 2z ;  acc = c0*s + c1*t1
__global__ void combine_first(const float4* __restrict__ s,
                              const float4* __restrict__ z,
                              float4* __restrict__ t1,
                              float4* __restrict__ acc,
                              float c0, float c1, int n4) {
    int i = blockIdx.x * blockDim.x + threadIdx.x;
    if (i >= n4) return;
    float4 sv = s[i];
    float4 zv = z[i];
    float4 t;
    t.x = sv.x - 2.f * zv.x;
    t.y = sv.y - 2.f * zv.y;
    t.z = sv.z - 2.f * zv.z;
    t.w = sv.w - 2.f * zv.w;
    t1[i] = t;
    float4 o;
    o.x = c0 * sv.x + c1 * t.x;
    o.y = c0 * sv.y + c1 * t.y;
    o.z = c0 * sv.z + c1 * t.z;
    o.w = c0 * sv.w + c1 * t.w;
    acc[i] = o;
}

// Recurrence step:  t2 = 2*(t1 - 2z) - t0 = 2*t1 - 4*z - t0 ;  acc += ck*t2
__global__ void combine_step(const float4* __restrict__ t1,
                             const float4* __restrict__ t0,
                             const float4* __restrict__ z,
                             float4* __restrict__ t2,
                             float4* __restrict__ acc,
                             float ck, int n4) {
    int i = blockIdx.x * blockDim.x + threadIdx.x;
    if (i >= n4) return;
    float4 a = t1[i];
    float4 b = t0[i];
    float4 zv = z[i];
    float4 t;
    t.x = 2.f * a.x - 4.f * zv.x - b.x;
    t.y = 2.f * a.y - 4.f * zv.y - b.y;
    t.z = 2.f * a.z - 4.f * zv.z - b.z;
    t.w = 2.f * a.w - 4.f * zv.w - b.w;
    t2[i] = t;
    float4 o = acc[i];
    o.x += ck * t.x;
    o.y += ck * t.y;
    o.z += ck * t.z;
    o.w += ck * t.w;
    acc[i] = o;
}

// ---------------------------------------------------------------------------
// Tiled transpose: in is [rows][cols], out is [cols][rows].
__global__ void transpose_k(const float* __restrict__ in,
                            float* __restrict__ out,
                            int rows, int cols) {
    __shared__ float tile[32][33];
    int cb = blockIdx.x * 32;
    int rb = blockIdx.y * 32;
    int c = cb + threadIdx.x;
#pragma unroll
    for (int j = threadIdx.y; j < 32; j += 8) {
        int r = rb + j;
        tile[j][threadIdx.x] = (c < cols && r < rows) ? in[(size_t)r * cols + c] : 0.f;
    }
    __syncthreads();
    int r2 = rb + threadIdx.x;
#pragma unroll
    for (int j = threadIdx.y; j < 32; j += 8) {
        int c2 = cb + j;
        if (c2 < cols && r2 < rows)
            out[(size_t)c2 * rows + r2] = tile[threadIdx.x][j];
    }
}

// ---------------------------------------------------------------------------
// Host-side Chebyshev coefficient computation, replicating the numpy
// reference exactly (double precision, round-half-even via nearbyint).
static void compute_coeffs(float c[ORDER + 1]) {
    const int order = ORDER;
    const int flat = 2;
    double xv[ORDER + 1], tgt[ORDER + 1], nodes[ORDER + 1];
    for (int i = 0; i <= order; i++) {
        double x = cos((double)(order - i) / (double)order * M_PI);
        xv[i] = nearbyint(x * 1000.0) / 1000.0;
        double t = (xv[i] < 0.0) ? pow(-xv[i], (double)flat) * 0.5 + 0.5
                                 : pow(xv[i], (double)flat) * (-0.5) + 0.5;
        tgt[i] = nearbyint(t * 1000.0) / 1000.0;
    }
    for (int k = 1; k <= order + 1; k++)
        nodes[k - 1] = cos(((double)order + 1.0 + 0.5 - (double)k) /
                           (double)(order + 1) * M_PI);

    double prev2[ORDER + 1], prev1[ORDER + 1], cur[ORDER + 1];
    double cd[ORDER + 1];
    for (int j = 0; j <= order; j++) {
        prev2[j] = tgt[j];
        prev1[j] = nodes[j] * tgt[j];
    }
    cd[0] = 0.0; cd[1] = 0.0;
    for (int j = 0; j <= order; j++) { cd[0] += prev2[j]; cd[1] += prev1[j]; }
    for (int m = 2; m <= order; m++) {
        cd[m] = 0.0;
        for (int j = 0; j <= order; j++) {
            cur[j] = 2.0 * nodes[j] * prev1[j] - prev2[j];
            cd[m] += cur[j];
        }
        for (int j = 0; j <= order; j++) { prev2[j] = prev1[j]; prev1[j] = cur[j]; }
    }
    for (int m = 0; m <= order; m++) cd[m] *= 2.0 / (double)(order + 1);
    cd[0] /= 2.0;
    for (int m = 0; m <= order; m++) c[m] = (float)cd[m];
}

// ---------------------------------------------------------------------------
extern "C" void kernel_launch(void* const* d_in, const int* in_sizes, int n_in,
                              void* d_out, int out_size) {
    const float* signal = (const float*)d_in[0];   // [64, 50000]
    const float* vals   = (const float*)d_in[1];   // [NNZ]
    const int*   row    = (const int*)d_in[2];     // [NNZ] user idx
    const int*   col    = (const int*)d_in[3];     // [NNZ] item idx
    float* out = (float*)d_out;                    // [64, 50000]
    const int nnz = in_sizes[1];

    float c[ORDER + 1];
    compute_coeffs(c);

    float *t0, *t1, *t2, *acc, *y, *z;
    cudaGetSymbolAddress((void**)&t0,  g_b0);
    cudaGetSymbolAddress((void**)&t1,  g_b1);
    cudaGetSymbolAddress((void**)&t2,  g_b2);
    cudaGetSymbolAddress((void**)&acc, g_acc);
    cudaGetSymbolAddress((void**)&y,   g_y);
    cudaGetSymbolAddress((void**)&z,   g_z);

    const int NM  = N_ITEMS * BATCH;       // 3.2M
    const int N4  = NM / 4;                // 800K float4
    const int Y4  = (N_USERS * BATCH) / 4; // 1.6M float4
    const int TPB = 256;
    const int eBlocks = (nnz * 16 + TPB - 1) / TPB;
    const int c4Blocks = (N4 + TPB - 1) / TPB;
    const int y4Blocks = (Y4 + TPB - 1) / TPB;

    // s = signal.T  -> t0  (item-major [N_ITEMS][64])
    {
        dim3 tb(32, 8);
        dim3 gb((N_ITEMS + 31) / 32, (BATCH + 31) / 32);
        transpose_k<<<gb, tb>>>(signal, t0, BATCH, N_ITEMS);
    }

    // ---- t1 = lap(s) ----
    zero_k<<<y4Blocks, TPB>>>((float4*)y, Y4);
    spmm_scatter<<<eBlocks, TPB>>>(t0, y, vals, col, row, nnz);  // y[row]+=v*x[col]
    zero_k<<<c4Blocks, TPB>>>((float4*)z, N4);
    spmm_scatter<<<eBlocks, TPB>>>(y, z, vals, row, col, nnz);   // z[col]+=v*y[row]
    combine_first<<<c4Blocks, TPB>>>((const float4*)t0, (const float4*)z,
                                     (float4*)t1, (float4*)acc, c[0], c[1], N4);

    // ---- t_k = 2*lap(t_{k-1}) - t_{k-2},  acc += c_k * t_k ----
    float *p0 = t0, *p1 = t1, *p2 = t2;
    for (int k = 2; k <= ORDER; k++) {
        zero_k<<<y4Blocks, TPB>>>((float4*)y, Y4);
        spmm_scatter<<<eBlocks, TPB>>>(p1, y, vals, col, row, nnz);
        zero_k<<<c4Blocks, TPB>>>((float4*)z, N4);
        spmm_scatter<<<eBlocks, TPB>>>(y, z, vals, row, col, nnz);
        combine_step<<<c4Blocks, TPB>>>((const float4*)p1, (const float4*)p0,
                                        (const float4*)z, (float4*)p2,
                                        (float4*)acc, c[k], N4);
        float* tmp = p0; p0 = p1; p1 = p2; p2 = tmp;
    }

    // out = acc.T  ([N_ITEMS][64] -> [64][N_ITEMS])
    {
        dim3 tb(32, 8);
        dim3 gb((BATCH + 31) / 32, (N_ITEMS + 31) / 32);
        transpose_k<<<gb, tb>>>(acc, out, N_ITEMS, BATCH);
    }
}

// round 6
// speedup vs baseline: 1.7147x; 1.7147x over previous
#include <cuda_runtime.h>
#include <cuda_bf16.h>
#include <math.h>

#define N_USERS 100000
#define N_ITEMS 50000
#define BATCH   64
#define ORDER   8
#define NNZ_MAX 1600000

// ---------------------------------------------------------------------------
// Scratch (device globals — no allocation allowed)
// Dense states, item-major [N_ITEMS][64]
__device__ __align__(16) float g_b0[N_ITEMS * BATCH];
__device__ __align__(16) float g_b1[N_ITEMS * BATCH];
__device__ __align__(16) float g_b2[N_ITEMS * BATCH];
__device__ __align__(16) float g_acc[N_ITEMS * BATCH];
__device__ __align__(16) float g_y[N_USERS * BATCH];

// CSR structures (rebuilt every launch; deterministic work)
__device__ int   g_uptr[N_USERS + 1];
__device__ int   g_ucur[N_USERS];
__device__ int   g_uidx[NNZ_MAX];
__device__ float g_uval[NNZ_MAX];
__device__ int   g_iptr[N_ITEMS + 1];
__device__ int   g_icur[N_ITEMS];
__device__ int   g_iidx[NNZ_MAX];
__device__ float g_ival[NNZ_MAX];
__device__ int   g_ucnt[N_USERS];
__device__ int   g_icnt[N_ITEMS];

// ---------------------------------------------------------------------------
__global__ void zero_int2(int* __restrict__ a, int na, int* __restrict__ b, int nb) {
    int i = blockIdx.x * blockDim.x + threadIdx.x;
    if (i < na) a[i] = 0;
    if (i < nb) b[i] = 0;
}

// Degree histogram for both directions in one pass
__global__ void hist_k(const int* __restrict__ row, const int* __restrict__ col,
                       int* __restrict__ ucnt, int* __restrict__ icnt, int nnz) {
    int e = blockIdx.x * blockDim.x + threadIdx.x;
    if (e >= nnz) return;
    atomicAdd(ucnt + __ldg(row + e), 1);
    atomicAdd(icnt + __ldg(col + e), 1);
}

// Single-block exclusive scan: cnt[0..n) -> ptr[0..n] and cur[0..n)
__global__ void scan_k(const int* __restrict__ cnt, int* __restrict__ ptr,
                       int* __restrict__ cur, int n) {
    __shared__ int ssum[1024];
    int t = threadIdx.x;
    int chunk = (n + 1023) / 1024;
    int begin = t * chunk;
    int end = min(begin + chunk, n);
    int s = 0;
    for (int i = begin; i < end; i++) s += cnt[i];
    ssum[t] = s;
    __syncthreads();
    for (int d = 1; d < 1024; d <<= 1) {
        int tmp = (t >= d) ? ssum[t - d] : 0;
        __syncthreads();
        ssum[t] += tmp;
        __syncthreads();
    }
    int off = ssum[t] - s;   // exclusive prefix of this thread's chunk
    for (int i = begin; i < end; i++) {
        ptr[i] = off;
        cur[i] = off;
        off += cnt[i];
    }
    if (begin < n && end == n) ptr[n] = off;
}

// Scatter edges into both CSR structures
__global__ void csr_fill(const int* __restrict__ row, const int* __restrict__ col,
                         const float* __restrict__ vals,
                         int* __restrict__ ucur, int* __restrict__ uidx, float* __restrict__ uval,
                         int* __restrict__ icur, int* __restrict__ iidx, float* __restrict__ ival,
                         int nnz) {
    int e = blockIdx.x * blockDim.x + threadIdx.x;
    if (e >= nnz) return;
    int r = __ldg(row + e);
    int c = __ldg(col + e);
    float v = __ldg(vals + e);
    int pu = atomicAdd(ucur + r, 1);
    uidx[pu] = c; uval[pu] = v;
    int pi = atomicAdd(icur + c, 1);
    iidx[pi] = r; ival[pi] = v;
}

// ---------------------------------------------------------------------------
// Gather accumulate helper: 2-deep software pipeline over the edge list to
// keep >=2 independent LDG.128 in flight per thread (raises MLP_eff).
__device__ __forceinline__ float4 gather_row(const float* __restrict__ x,
                                             const int* __restrict__ idx,
                                             const float* __restrict__ val,
                                             int s, int e, int t) {
    float4 acc = make_float4(0.f, 0.f, 0.f, 0.f);
    int j = s;
    if (j < e) {
        int ix0 = __ldg(idx + j);
        float v0 = __ldg(val + j);
        for (; j + 1 < e; j++) {
            int ix1 = __ldg(idx + j + 1);       // prefetch next index/val
            float v1 = __ldg(val + j + 1);
            float4 xv = __ldg((const float4*)(x + (ix0 << 6)) + t);
            acc.x += v0 * xv.x; acc.y += v0 * xv.y;
            acc.z += v0 * xv.z; acc.w += v0 * xv.w;
            ix0 = ix1; v0 = v1;
        }
        float4 xv = __ldg((const float4*)(x + (ix0 << 6)) + t);
        acc.x += v0 * xv.x; acc.y += v0 * xv.y;
        acc.z += v0 * xv.z; acc.w += v0 * xv.w;
    }
    return acc;
}

// Gather SpMM (user direction): y[r][:] = sum_e val[e] * x[idx[e]][:]
// 16 threads per row, each owns one float4 of the 64-wide state.
__global__ __launch_bounds__(256) void spmm_user(
        const float* __restrict__ x, float* __restrict__ y,
        const int* __restrict__ ptr, const int* __restrict__ idx,
        const float* __restrict__ val, int nrows) {
    int gid = blockIdx.x * blockDim.x + threadIdx.x;
    int r = gid >> 4;
    if (r >= nrows) return;
    int t = gid & 15;
    int s = __ldg(ptr + r), e = __ldg(ptr + r + 1);
    float4 acc = gather_row(x, idx, val, s, e, t);
    ((float4*)(y + (r << 6)))[t] = acc;
}

// Item-direction SpMM fused with first Chebyshev step:
//   z = A^T y ;  t1 = s - 2z ;  acc = c0*s + c1*t1
__global__ __launch_bounds__(256) void spmm_item_first(
        const float* __restrict__ y,
        const int* __restrict__ ptr, const int* __restrict__ idx,
        const float* __restrict__ val,
        const float* __restrict__ sbuf,
        float* __restrict__ t1, float* __restrict__ acc,
        float c0, float c1, int nrows) {
    int gid = blockIdx.x * blockDim.x + threadIdx.x;
    int r = gid >> 4;
    if (r >= nrows) return;
    int t = gid & 15;
    int s = __ldg(ptr + r), e = __ldg(ptr + r + 1);
    float4 z = gather_row(y, idx, val, s, e, t);
    int o = (r << 6) + t * 4;
    float4 sv = *(const float4*)(sbuf + o);
    float4 tv;
    tv.x = sv.x - 2.f * z.x; tv.y = sv.y - 2.f * z.y;
    tv.z = sv.z - 2.f * z.z; tv.w = sv.w - 2.f * z.w;
    *(float4*)(t1 + o) = tv;
    float4 ov;
    ov.x = c0 * sv.x + c1 * tv.x; ov.y = c0 * sv.y + c1 * tv.y;
    ov.z = c0 * sv.z + c1 * tv.z; ov.w = c0 * sv.w + c1 * tv.w;
    *(float4*)(acc + o) = ov;
}

// Item-direction SpMM fused with Chebyshev recurrence step:
//   z = A^T y ; t2 = 2*t1 - 4*z - t0 ; acc += ck * t2
__global__ __launch_bounds__(256) void spmm_item_step(
        const float* __restrict__ y,
        const int* __restrict__ ptr, const int* __restrict__ idx,
        const float* __restrict__ val,
        const float* __restrict__ t1, const float* __restrict__ t0,
        float* __restrict__ t2, float* __restrict__ acc,
        float ck, int nrows) {
    int gid = blockIdx.x * blockDim.x + threadIdx.x;
    int r = gid >> 4;
    if (r >= nrows) return;
    int t = gid & 15;
    int s = __ldg(ptr + r), e = __ldg(ptr + r + 1);
    float4 z = gather_row(y, idx, val, s, e, t);
    int o = (r << 6) + t * 4;
    float4 a = *(const float4*)(t1 + o);
    float4 b = *(const float4*)(t0 + o);
    float4 tv;
    tv.x = 2.f * a.x - 4.f * z.x - b.x;
    tv.y = 2.f * a.y - 4.f * z.y - b.y;
    tv.z = 2.f * a.z - 4.f * z.z - b.z;
    tv.w = 2.f * a.w - 4.f * z.w - b.w;
    *(float4*)(t2 + o) = tv;
    float4 ov = *(const float4*)(acc + o);
    ov.x += ck * tv.x; ov.y += ck * tv.y;
    ov.z += ck * tv.z; ov.w += ck * tv.w;
    *(float4*)(acc + o) = ov;
}

// ---------------------------------------------------------------------------
// Tiled transpose: in is [rows][cols], out is [cols][rows].
__global__ void transpose_k(const float* __restrict__ in, float* __restrict__ out,
                            int rows, int cols) {
    __shared__ float tile[32][33];
    int cb = blockIdx.x * 32;
    int rb = blockIdx.y * 32;
    int c = cb + threadIdx.x;
#pragma unroll
    for (int j = threadIdx.y; j < 32; j += 8) {
        int r = rb + j;
        tile[j][threadIdx.x] = (c < cols && r < rows) ? in[(size_t)r * cols + c] : 0.f;
    }
    __syncthreads();
    int r2 = rb + threadIdx.x;
#pragma unroll
    for (int j = threadIdx.y; j < 32; j += 8) {
        int c2 = cb + j;
        if (c2 < cols && r2 < rows)
            out[(size_t)c2 * rows + r2] = tile[threadIdx.x][j];
    }
}

// ---------------------------------------------------------------------------
// Host-side Chebyshev coefficients (double precision, round-half-even,
// replicating the numpy reference exactly)
static void compute_coeffs(float c[ORDER + 1]) {
    const int order = ORDER;
    const int flat = 2;
    double xv[ORDER + 1], tgt[ORDER + 1], nodes[ORDER + 1];
    for (int i = 0; i <= order; i++) {
        double x = cos((double)(order - i) / (double)order * M_PI);
        xv[i] = nearbyint(x * 1000.0) / 1000.0;
        double t = (xv[i] < 0.0) ? pow(-xv[i], (double)flat) * 0.5 + 0.5
                                 : pow(xv[i], (double)flat) * (-0.5) + 0.5;
        tgt[i] = nearbyint(t * 1000.0) / 1000.0;
    }
    for (int k = 1; k <= order + 1; k++)
        nodes[k - 1] = cos(((double)order + 1.0 + 0.5 - (double)k) /
                           (double)(order + 1) * M_PI);
    double prev2[ORDER + 1], prev1[ORDER + 1], cur[ORDER + 1];
    double cd[ORDER + 1];
    for (int j = 0; j <= order; j++) {
        prev2[j] = tgt[j];
        prev1[j] = nodes[j] * tgt[j];
    }
    cd[0] = 0.0; cd[1] = 0.0;
    for (int j = 0; j <= order; j++) { cd[0] += prev2[j]; cd[1] += prev1[j]; }
    for (int m = 2; m <= order; m++) {
        cd[m] = 0.0;
        for (int j = 0; j <= order; j++) {
            cur[j] = 2.0 * nodes[j] * prev1[j] - prev2[j];
            cd[m] += cur[j];
        }
        for (int j = 0; j <= order; j++) { prev2[j] = prev1[j]; prev1[j] = cur[j]; }
    }
    for (int m = 0; m <= order; m++) cd[m] *= 2.0 / (double)(order + 1);
    cd[0] /= 2.0;
    for (int m = 0; m <= order; m++) c[m] = (float)cd[m];
}

// ---------------------------------------------------------------------------
extern "C" void kernel_launch(void* const* d_in, const int* in_sizes, int n_in,
                              void* d_out, int out_size) {
    const float* signal = (const float*)d_in[0];   // [64, 50000]
    const float* vals   = (const float*)d_in[1];   // [NNZ]
    const int*   row    = (const int*)d_in[2];     // [NNZ] user idx
    const int*   col    = (const int*)d_in[3];     // [NNZ] item idx
    float* out = (float*)d_out;                    // [64, 50000]
    const int nnz = in_sizes[1];

    float c[ORDER + 1];
    compute_coeffs(c);

    float *t0, *t1, *t2, *acc, *y;
    int *uptr, *ucur, *uidx, *iptr, *icur, *iidx, *ucnt, *icnt;
    float *uval, *ival;
    cudaGetSymbolAddress((void**)&t0,   g_b0);
    cudaGetSymbolAddress((void**)&t1,   g_b1);
    cudaGetSymbolAddress((void**)&t2,   g_b2);
    cudaGetSymbolAddress((void**)&acc,  g_acc);
    cudaGetSymbolAddress((void**)&y,    g_y);
    cudaGetSymbolAddress((void**)&uptr, g_uptr);
    cudaGetSymbolAddress((void**)&ucur, g_ucur);
    cudaGetSymbolAddress((void**)&uidx, g_uidx);
    cudaGetSymbolAddress((void**)&uval, g_uval);
    cudaGetSymbolAddress((void**)&iptr, g_iptr);
    cudaGetSymbolAddress((void**)&icur, g_icur);
    cudaGetSymbolAddress((void**)&iidx, g_iidx);
    cudaGetSymbolAddress((void**)&ival, g_ival);
    cudaGetSymbolAddress((void**)&ucnt, g_ucnt);
    cudaGetSymbolAddress((void**)&icnt, g_icnt);

    const int TPB = 256;
    const int eB = (nnz + TPB - 1) / TPB;
    const int uB = (N_USERS * 16 + TPB - 1) / TPB;   // spmm_user grid
    const int iB = (N_ITEMS * 16 + TPB - 1) / TPB;   // spmm_item grid

    // ---- CSR build (amortized over 16 SpMM passes) ----
    zero_int2<<<(N_USERS + TPB - 1) / TPB, TPB>>>(ucnt, N_USERS, icnt, N_ITEMS);
    hist_k<<<eB, TPB>>>(row, col, ucnt, icnt, nnz);
    scan_k<<<1, 1024>>>(ucnt, uptr, ucur, N_USERS);
    scan_k<<<1, 1024>>>(icnt, iptr, icur, N_ITEMS);
    csr_fill<<<eB, TPB>>>(row, col, vals, ucur, uidx, uval, icur, iidx, ival, nnz);

    // s = signal.T -> t0 (item-major)
    {
        dim3 tb(32, 8);
        dim3 gb((N_ITEMS + 31) / 32, (BATCH + 31) / 32);
        transpose_k<<<gb, tb>>>(signal, t0, BATCH, N_ITEMS);
    }

    // ---- t1 = lap(s); acc = c0*s + c1*t1 ----
    spmm_user<<<uB, TPB>>>(t0, y, uptr, uidx, uval, N_USERS);
    spmm_item_first<<<iB, TPB>>>(y, iptr, iidx, ival, t0, t1, acc, c[0], c[1], N_ITEMS);

    // ---- t_k = 2*lap(t_{k-1}) - t_{k-2}; acc += c_k*t_k ----
    float *p0 = t0, *p1 = t1, *p2 = t2;
    for (int k = 2; k <= ORDER; k++) {
        spmm_user<<<uB, TPB>>>(p1, y, uptr, uidx, uval, N_USERS);
        spmm_item_step<<<iB, TPB>>>(y, iptr, iidx, ival, p1, p0, p2, acc, c[k], N_ITEMS);
        float* tmp = p0; p0 = p1; p1 = p2; p2 = tmp;
    }

    // out = acc.T
    {
        dim3 tb(32, 8);
        dim3 gb((BATCH + 31) / 32, (N_ITEMS + 31) / 32);
        transpose_k<<<gb, tb>>>(acc, out, N_ITEMS, BATCH);
    }
}